// round 4
// baseline (speedup 1.0000x reference)
#include <cuda_runtime.h>
#include <cstdint>

// Problem shape (fixed by the dataset)
#define BB 4
#define NN 65536
#define NHH 7
#define EE 128

static const long long PAIRS     = (long long)BB * NN;          // 262,144 (b,n) pairs
static const long long ROWS      = PAIRS * NHH;                 // 1,835,008 gather rows
static const long long XNH_ELEMS = ROWS * EE;                   // 234,881,024 floats

// One warp per TWO (b,n) pairs: 2 index chains overlap, 14 independent 512B
// gather reads in flight per warp (7KB outstanding), streaming stores.
__global__ void __launch_bounds__(256) gather_nh2_kernel(
    const float4*        __restrict__ x,     // [B*N*32] float4 (B,N,1,128 fp32)
    const int*           __restrict__ adjc,  // [N*NH]
    const unsigned char* __restrict__ mi,    // [N*NH] bool bytes
    const int*           __restrict__ lidx,  // [B*N]
    const int*           __restrict__ bsi,   // [B]
    const int*           __restrict__ slevel,// [1] or null
    float4*              __restrict__ out,   // [ROWS*32] float4
    float*               __restrict__ mout)  // [ROWS] or null
{
    long long tid  = (long long)blockIdx.x * blockDim.x + threadIdx.x;
    long long warp = tid >> 5;
    int lane = (int)(tid & 31);
    long long p0 = warp * 2;                  // first (b,n) pair
    if (p0 >= PAIRS) return;

    int lvl = (slevel != nullptr) ? __ldg(&slevel[0]) : 0;

    int bArr[2], liArr[2];
    #pragma unroll
    for (int j = 0; j < 2; j++) {
        long long p = p0 + j;
        int b = (int)(p / NN);
        int n = (int)(p % NN);
        bArr[j]  = b;
        liArr[j] = __ldg(&lidx[b * NN + n]);  // two chains issue together
    }

    int idx[2][NHH];
    #pragma unroll
    for (int j = 0; j < 2; j++) {
        int off = __ldg(&bsi[bArr[j]]) << (2 * lvl);   // bsi * 4^lvl
        #pragma unroll
        for (int h = 0; h < NHH; h++)
            idx[j][h] = __ldg(&adjc[liArr[j] * NHH + h]) - off;
    }

    // 14 independent gather reads, front-batched
    float4 v[2][NHH];
    #pragma unroll
    for (int j = 0; j < 2; j++) {
        const float4* xb = x + (long long)bArr[j] * NN * 32;
        #pragma unroll
        for (int h = 0; h < NHH; h++)
            v[j][h] = __ldg(&xb[(long long)idx[j][h] * 32 + lane]);
    }

    #pragma unroll
    for (int j = 0; j < 2; j++) {
        float4* o = out + (p0 + j) * NHH * 32;
        #pragma unroll
        for (int h = 0; h < NHH; h++)
            __stcs(&o[h * 32 + lane], v[j][h]);
    }

    if (mout != nullptr && lane < 2 * NHH) {
        int j = lane / NHH;                   // lanes 0..13 cover both pairs
        int h = lane % NHH;
        mout[(p0 + j) * NHH + h] =
            __ldg(&mi[liArr[j] * NHH + h]) ? 1.0f : 0.0f;
    }
}

extern "C" void kernel_launch(void* const* d_in, const int* in_sizes, int n_in,
                              void* d_out, int out_size)
{
    const float4*        x    = (const float4*)d_in[0];
    const int*           adjc = (const int*)d_in[1];
    const unsigned char* mi   = (const unsigned char*)d_in[2];
    const int*           lidx = (const int*)d_in[3];
    const int*           bsi  = (const int*)d_in[4];
    const int*           slv  = (n_in >= 6) ? (const int*)d_in[5] : nullptr;

    float* out  = (float*)d_out;
    float* mout = ((long long)out_size > XNH_ELEMS) ? out + XNH_ELEMS : nullptr;

    long long warps  = (PAIRS + 1) / 2;       // one warp per 2 pairs
    long long threads_total = warps * 32;
    int tpb = 256;
    long long blocks = (threads_total + tpb - 1) / tpb;
    gather_nh2_kernel<<<(unsigned int)blocks, tpb>>>(
        x, adjc, mi, lidx, bsi, slv, (float4*)out, mout);
}

// round 6
// speedup vs baseline: 1.0090x; 1.0090x over previous
#include <cuda_runtime.h>
#include <cstdint>

// Problem shape (fixed by the dataset)
#define BB 4
#define NN 65536
#define NHH 7
#define EE 128

static const long long PAIRS     = (long long)BB * NN;          // 262,144 (b,n) pairs
static const long long ROWS      = PAIRS * NHH;                 // 1,835,008 gather rows
static const long long XNH_ELEMS = ROWS * EE;                   // 234,881,024 floats

// One warp per (b,n). Before gathering, the warp L2-prefetches its OWN x row:
// across the grid this reads all of x sequentially into L2, so the random
// gathers hit L2 instead of triggering randomly-ordered DRAM reads interleaved
// into the sequential write stream. 7 independent 512B gathers (MLP=7),
// streaming stores so the 939MB output doesn't evict the x slice from L2.
__global__ void __launch_bounds__(256) gather_nh_kernel(
    const float4*        __restrict__ x,     // [B*N*32] float4 (B,N,1,128 fp32)
    const int*           __restrict__ adjc,  // [N*NH]
    const unsigned char* __restrict__ mi,    // [N*NH] bool bytes
    const int*           __restrict__ lidx,  // [B*N]
    const int*           __restrict__ bsi,   // [B]
    const int*           __restrict__ slevel,// [1] or null
    float4*              __restrict__ out,   // [ROWS*32] float4
    float*               __restrict__ mout)  // [ROWS] or null
{
    long long tid = (long long)blockIdx.x * blockDim.x + threadIdx.x;
    long long w   = tid >> 5;                 // (b,n) pair index
    int lane = (int)(tid & 31);
    if (w >= PAIRS) return;

    int b = (int)(w / NN);
    int n = (int)(w % NN);

    // Sequential L2 prefetch of this pair's own x row (4 x 128B lines).
    {
        const char* xrow = (const char*)(x + w * 32);
        if (lane < 4)
            asm volatile("prefetch.global.L2 [%0];" :: "l"(xrow + lane * 128));
    }

    int li  = __ldg(&lidx[b * NN + n]);
    int lvl = (slevel != nullptr) ? __ldg(&slevel[0]) : 0;
    int off = __ldg(&bsi[b]) << (2 * lvl);    // bsi * 4^lvl

    int idx[NHH];
    #pragma unroll
    for (int h = 0; h < NHH; h++)
        idx[h] = __ldg(&adjc[li * NHH + h]) - off;

    const float4* xb = x + (long long)b * NN * 32;

    float4 v[NHH];
    #pragma unroll
    for (int h = 0; h < NHH; h++)             // 7 independent 512B gather reads
        v[h] = __ldg(&xb[(long long)idx[h] * 32 + lane]);

    float4* o = out + w * NHH * 32;
    #pragma unroll
    for (int h = 0; h < NHH; h++)
        __stcs(&o[h * 32 + lane], v[h]);

    if (mout != nullptr && lane < NHH)
        mout[w * NHH + lane] = __ldg(&mi[li * NHH + lane]) ? 1.0f : 0.0f;
}

extern "C" void kernel_launch(void* const* d_in, const int* in_sizes, int n_in,
                              void* d_out, int out_size)
{
    const float4*        x    = (const float4*)d_in[0];
    const int*           adjc = (const int*)d_in[1];
    const unsigned char* mi   = (const unsigned char*)d_in[2];
    const int*           lidx = (const int*)d_in[3];
    const int*           bsi  = (const int*)d_in[4];
    const int*           slv  = (n_in >= 6) ? (const int*)d_in[5] : nullptr;

    float* out  = (float*)d_out;
    float* mout = ((long long)out_size > XNH_ELEMS) ? out + XNH_ELEMS : nullptr;

    long long threads_total = PAIRS * 32;     // one warp per (b,n)
    int tpb = 256;
    long long blocks = (threads_total + tpb - 1) / tpb;
    gather_nh_kernel<<<(unsigned int)blocks, tpb>>>(
        x, adjc, mi, lidx, bsi, slv, (float4*)out, mout);
}